// round 5
// baseline (speedup 1.0000x reference)
#include <cuda_runtime.h>
#include <math.h>
#include <stdint.h>

#define SEQ   512
#define BATCH 64
#define NIN   1024
#define NHID  1024
#define G4    4096
#define NBLK  128
#define NTHR  512

__device__ float g_xw[(size_t)SEQ * BATCH * G4];
__device__ float g_hs[(size_t)SEQ * BATCH * NHID];
__device__ float g_c [(size_t)BATCH * NHID];
__device__ unsigned g_arr;
__device__ unsigned g_gen;

__device__ __forceinline__ unsigned long long pk2(float x) {
    unsigned long long r;
    asm("mov.b64 %0, {%1, %1};" : "=l"(r) : "f"(x));
    return r;
}
__device__ __forceinline__ void upk2(unsigned long long v, float& lo, float& hi) {
    asm("mov.b64 {%0, %1}, %2;" : "=f"(lo), "=f"(hi) : "l"(v));
}
__device__ __forceinline__ void ffma2(unsigned long long& d,
                                      unsigned long long a,
                                      unsigned long long b) {
    asm("fma.rn.f32x2 %0, %1, %2, %0;" : "+l"(d) : "l"(a), "l"(b));
}
__device__ __forceinline__ void cp16(void* dst, const void* src) {
    unsigned d = (unsigned)__cvta_generic_to_shared(dst);
    asm volatile("cp.async.cg.shared.global [%0], [%1], 16;\n" :: "r"(d), "l"(src));
}

// ---------------------------------------------------------------------------
// Persistent LSTM recurrence. 128 blocks x 512 thr, all co-resident.
// smem: [0,131072) ws = w slice [k=1024][r=32]; [131072,+32K) hs buf0;
//       [+32K,+64K) hs buf1 ([b=64][k=128] floats, rows 512B);
//       reduction (8*512*16B = 64KB) aliases the hs buffers.
// Thread id = qk(8) x bg(8) x jl(8): k-eighth, batch-group(8), unit lane.
// ---------------------------------------------------------------------------
__global__ void __launch_bounds__(NTHR, 1) lstm_persist(
    const float* __restrict__ h0,
    const float* __restrict__ c0,
    const float* __restrict__ w_h)
{
    extern __shared__ char smem[];
    float* ws = (float*)smem;
    char* hsb[2] = { smem + 131072, smem + 131072 + 32768 };
    char* red    = smem + 131072;

    const int tid = threadIdx.x;
    const int j0  = blockIdx.x * 8;
    const int qk  = tid >> 6;
    const int bg  = (tid >> 3) & 7;
    const int jl  = tid & 7;
    const int b0  = bg * 8;
    // epilogue identity: slot2 = b*8 + jl  ->  b = tid>>3, jl = tid&7
    const int eb  = tid >> 3;
    const int ej  = j0 + (tid & 7);

    // w slice once: [g*NHID + j0+jj][k] -> ws[k*32 + jj*4+g]
#pragma unroll
    for (int q = 0; q < 16; q++) {
        const int s  = tid + NTHR * q;
        const int r  = s & 31;
        const int k4 = s >> 5;
        const int g  = r & 3, jj = r >> 2;
        const float4 v = *(const float4*)(w_h
            + (size_t)(g * NHID + j0 + jj) * NHID + k4 * 4);
        ws[(k4 * 4 + 0) * 32 + r] = v.x;
        ws[(k4 * 4 + 1) * 32 + r] = v.y;
        ws[(k4 * 4 + 2) * 32 + r] = v.z;
        ws[(k4 * 4 + 3) * 32 + r] = v.w;
    }

    float creg = c0[(size_t)eb * NHID + ej];
    __syncthreads();

    for (int t = 0; t < SEQ; t++) {
        const float* hp = t ? (g_hs + (size_t)(t - 1) * BATCH * NHID) : h0;

        float xwv[4];
        {
            const float* xwt = g_xw + (size_t)t * BATCH * G4
                                    + (size_t)eb * G4 + ej;
#pragma unroll
            for (int g = 0; g < 4; g++) xwv[g] = xwt[g * NHID];
        }

        unsigned long long acc[8][2];
#pragma unroll
        for (int i = 0; i < 8; i++) { acc[i][0] = 0ull; acc[i][1] = 0ull; }

        // prologue: tile 0 -> buf 0
#pragma unroll
        for (int q = 0; q < 4; q++) {
            const int s = tid + NTHR * q;
            const int b = s >> 5, cc = s & 31;
            cp16(hsb[0] + b * 512 + cc * 16, hp + (size_t)b * NHID + cc * 4);
        }
        asm volatile("cp.async.commit_group;\n" ::);

        int buf = 0;
        for (int tile = 0; tile < 8; tile++) {
            asm volatile("cp.async.wait_group 0;\n" ::);
            __syncthreads();
            if (tile < 7) {
                char* db = hsb[buf ^ 1];
                const int k0 = (tile + 1) * 128;
#pragma unroll
                for (int q = 0; q < 4; q++) {
                    const int s = tid + NTHR * q;
                    const int b = s >> 5, cc = s & 31;
                    cp16(db + b * 512 + cc * 16,
                         hp + (size_t)b * NHID + k0 + cc * 4);
                }
                asm volatile("cp.async.commit_group;\n" ::);
            }
            const char* hb = hsb[buf];
#pragma unroll
            for (int u = 0; u < 4; u++) {
                const int c16 = qk * 4 + u;
                float4 h4[8];
#pragma unroll
                for (int i = 0; i < 8; i++)
                    h4[i] = *(const float4*)(hb + (b0 + i) * 512 + c16 * 16);
#pragma unroll
                for (int kk = 0; kk < 4; kk++) {
                    const int k = tile * 128 + qk * 16 + u * 4 + kk;
                    const ulonglong2 wv = *(const ulonglong2*)(ws + k * 32 + jl * 4);
#pragma unroll
                    for (int i = 0; i < 8; i++) {
                        const unsigned long long hv = pk2((&h4[i].x)[kk]);
                        ffma2(acc[i][0], hv, wv.x);
                        ffma2(acc[i][1], hv, wv.y);
                    }
                }
            }
            buf ^= 1;
        }

        __syncthreads();   // tile reads done before red overwrites hs
#pragma unroll
        for (int i = 0; i < 8; i++) {
            const int slot2 = (b0 + i) * 8 + jl;
            ulonglong2 v; v.x = acc[i][0]; v.y = acc[i][1];
            *(ulonglong2*)(red + (((unsigned)(qk * 512 + slot2)) << 4)) = v;
        }
        __syncthreads();

        float a0 = xwv[0], a1 = xwv[1], a2 = xwv[2], a3 = xwv[3];
#pragma unroll
        for (int q2 = 0; q2 < 8; q2++) {
            const float4 v = *(const float4*)(red
                + (((unsigned)(q2 * 512 + tid)) << 4));
            a0 += v.x; a1 += v.y; a2 += v.z; a3 += v.w;
        }
        const float iS = 1.f / (1.f + expf(-a0));
        const float fS = 1.f / (1.f + expf(-a1));
        const float oS = 1.f / (1.f + expf(-a2));
        const float gT = tanhf(a3);
        creg = fS * creg + iS * gT;
        g_hs[(size_t)t * BATCH * NHID + (size_t)eb * NHID + ej]
            = oS * tanhf(creg);

        // grid barrier
        __threadfence();
        __syncthreads();
        if (tid == 0) {
            volatile unsigned* gp = &g_gen;
            const unsigned old = *gp;
            __threadfence();
            if (atomicAdd(&g_arr, 1u) == NBLK - 1) {
                atomicExch(&g_arr, 0u);
                __threadfence();
                atomicAdd(&g_gen, 1u);
            } else {
                while (*gp == old) { }
            }
            __threadfence();
        }
        __syncthreads();
    }

    g_c[(size_t)eb * NHID + ej] = creg;
}

// ---------------------------------------------------------------------------
// GEMM: C[M,N] = A[M,K] @ B[N,K]^T (+bias). 128x128, double-buffered, f32x2.
// ---------------------------------------------------------------------------
__global__ void __launch_bounds__(256) gemm_nt_bias(
    const float* __restrict__ A, const float* __restrict__ B,
    const float* __restrict__ bias, float* __restrict__ C,
    int M, int N, int K)
{
    __shared__ float As[2][8][128];
    __shared__ float Bs[2][8][128];
    const int tid  = threadIdx.x;
    const int row0 = blockIdx.y * 128;
    const int col0 = blockIdx.x * 128;
    const int lr = tid >> 1;
    const int lc = (tid & 1) << 2;
    const int tx = tid & 15;
    const int ty = tid >> 4;

    unsigned long long acc2[8][4];
#pragma unroll
    for (int i = 0; i < 8; i++)
#pragma unroll
        for (int j = 0; j < 4; j++) acc2[i][j] = 0ull;

    const float* Ab = A + (size_t)row0 * K;
    const float* Bb = B + (size_t)col0 * K;
    const int nT = K / 8;

    float4 a4 = *(const float4*)(Ab + (size_t)lr * K + lc);
    float4 b4 = *(const float4*)(Bb + (size_t)lr * K + lc);
    As[0][lc + 0][lr] = a4.x; As[0][lc + 1][lr] = a4.y;
    As[0][lc + 2][lr] = a4.z; As[0][lc + 3][lr] = a4.w;
    Bs[0][lc + 0][lr] = b4.x; Bs[0][lc + 1][lr] = b4.y;
    Bs[0][lc + 2][lr] = b4.z; Bs[0][lc + 3][lr] = b4.w;
    __syncthreads();

    for (int kt = 0; kt < nT; kt++) {
        const int cur = kt & 1;
        if (kt + 1 < nT) {
            const int k0 = (kt + 1) * 8;
            a4 = *(const float4*)(Ab + (size_t)lr * K + k0 + lc);
            b4 = *(const float4*)(Bb + (size_t)lr * K + k0 + lc);
        }
#pragma unroll
        for (int k = 0; k < 8; k++) {
            float ra[8];
            *(float4*)&ra[0] = *(const float4*)&As[cur][k][ty * 8];
            *(float4*)&ra[4] = *(const float4*)&As[cur][k][ty * 8 + 4];
            ulonglong2 rb0 = *(const ulonglong2*)&Bs[cur][k][tx * 8];
            ulonglong2 rb1 = *(const ulonglong2*)&Bs[cur][k][tx * 8 + 4];
#pragma unroll
            for (int i = 0; i < 8; i++) {
                const unsigned long long pa = pk2(ra[i]);
                ffma2(acc2[i][0], pa, rb0.x);
                ffma2(acc2[i][1], pa, rb0.y);
                ffma2(acc2[i][2], pa, rb1.x);
                ffma2(acc2[i][3], pa, rb1.y);
            }
        }
        if (kt + 1 < nT) {
            const int nxt = cur ^ 1;
            As[nxt][lc + 0][lr] = a4.x; As[nxt][lc + 1][lr] = a4.y;
            As[nxt][lc + 2][lr] = a4.z; As[nxt][lc + 3][lr] = a4.w;
            Bs[nxt][lc + 0][lr] = b4.x; Bs[nxt][lc + 1][lr] = b4.y;
            Bs[nxt][lc + 2][lr] = b4.z; Bs[nxt][lc + 3][lr] = b4.w;
            __syncthreads();
        }
    }

#pragma unroll
    for (int i = 0; i < 8; i++) {
        const int r = row0 + ty * 8 + i;
        float av[8];
#pragma unroll
        for (int j = 0; j < 4; j++) upk2(acc2[i][j], av[2 * j], av[2 * j + 1]);
#pragma unroll
        for (int j = 0; j < 8; j += 4) {
            const int c = col0 + tx * 8 + j;
            float4 v;
            v.x = av[j + 0]; v.y = av[j + 1];
            v.z = av[j + 2]; v.w = av[j + 3];
            if (bias) {
                v.x += bias[c + 0]; v.y += bias[c + 1];
                v.z += bias[c + 2]; v.w += bias[c + 3];
            }
            *(float4*)(C + (size_t)r * N + c) = v;
        }
    }
}

__global__ void copy_tail(float* __restrict__ out_h, float* __restrict__ out_c)
{
    const int i = blockIdx.x * blockDim.x + threadIdx.x;
    if (i < BATCH * NHID) {
        out_h[i] = g_hs[(size_t)(SEQ - 1) * BATCH * NHID + i];
        out_c[i] = g_c[i];
    }
}

extern "C" void kernel_launch(void* const* d_in, const int* in_sizes, int n_in,
                              void* d_out, int out_size)
{
    const float* x    = (const float*)d_in[0];
    const float* h0   = (const float*)d_in[1];
    const float* c0   = (const float*)d_in[2];
    const float* w_x  = (const float*)d_in[3];
    const float* w_h  = (const float*)d_in[4];
    const float* bias = (const float*)d_in[5];
    const float* w_o  = (const float*)d_in[6];
    float* out = (float*)d_out;

    float *xw, *hs;
    cudaGetSymbolAddress((void**)&xw, g_xw);
    cudaGetSymbolAddress((void**)&hs, g_hs);

    static int smem_set = 0;
    if (!smem_set) {
        cudaFuncSetAttribute(lstm_persist,
                             cudaFuncAttributeMaxDynamicSharedMemorySize,
                             196608);
        smem_set = 1;
    }

    // Phase 1: xw = x @ w_x^T + bias
    {
        dim3 grid(G4 / 128, (SEQ * BATCH) / 128);
        gemm_nt_bias<<<grid, 256>>>(x, w_x, bias, xw, SEQ * BATCH, G4, NIN);
    }

    // Phase 2: persistent recurrence (ONE launch)
    lstm_persist<<<NBLK, NTHR, 196608>>>(h0, c0, w_h);

    // Phase 3: pred = H @ w_o^T
    {
        dim3 grid(NHID / 128, (SEQ * BATCH) / 128);
        gemm_nt_bias<<<grid, 256>>>(hs, w_o, nullptr, out, SEQ * BATCH, NHID, NHID);
    }

    copy_tail<<<(BATCH * NHID + 255) / 256, 256>>>(
        out + (size_t)SEQ * BATCH * NHID,
        out + (size_t)SEQ * BATCH * NHID + BATCH * NHID);
}

// round 7
// speedup vs baseline: 1.3206x; 1.3206x over previous
#include <cuda_runtime.h>
#include <cuda_bf16.h>
#include <math.h>
#include <stdint.h>

#define SEQ 512
#define BATCH 64
#define NHID 1024
#define G4 4096
#define RBLK 128
#define RTHR 256

__device__ float g_xw[(size_t)SEQ*BATCH*G4];
__device__ float g_hs[(size_t)SEQ*BATCH*NHID];
__device__ float g_c[(size_t)BATCH*NHID];
__device__ unsigned g_arr, g_gen;
__device__ uint4 g_wt[2][RBLK][16][256];   // [split][blk][k64-chunk][32r x 128B]
__device__ uint4 g_ht[2][2][16][512];      // [split][buf][k64-chunk][64b x 128B]

__device__ __forceinline__ unsigned long long pk2(float x){
    unsigned long long r; asm("mov.b64 %0,{%1,%1};":"=l"(r):"f"(x)); return r; }
__device__ __forceinline__ void upk2(unsigned long long v,float&a,float&b){
    asm("mov.b64 {%0,%1},%2;":"=f"(a),"=f"(b):"l"(v)); }
__device__ __forceinline__ void ffma2(unsigned long long&d,unsigned long long a,unsigned long long b){
    asm("fma.rn.f32x2 %0,%1,%2,%0;":"+l"(d):"l"(a),"l"(b)); }
__device__ __forceinline__ void cp16(uint32_t d,const void*s){
    asm volatile("cp.async.cg.shared.global [%0],[%1],16;"::"r"(d),"l"(s)); }
__device__ __forceinline__ uint32_t s2u(const void*p){
    uint32_t a; asm("{.reg .u64 t; cvta.to.shared.u64 t,%1; cvt.u32.u64 %0,t;}":"=r"(a):"l"(p)); return a; }
__host__ __device__ __forceinline__ uint32_t swz(uint32_t o){ return o^((o>>3)&0x70); }
__device__ __forceinline__ void ldm4(uint32_t*r,uint32_t a){
    asm volatile("ldmatrix.sync.aligned.m8n8.x4.shared.b16 {%0,%1,%2,%3},[%4];"
        :"=r"(r[0]),"=r"(r[1]),"=r"(r[2]),"=r"(r[3]):"r"(a)); }
__device__ __forceinline__ void hmma(float*d,const uint32_t*a,const uint32_t*b){
    asm volatile("mma.sync.aligned.m16n8k16.row.col.f32.bf16.bf16.f32 "
        "{%0,%1,%2,%3},{%4,%5,%6,%7},{%8,%9},{%0,%1,%2,%3};"
        :"+f"(d[0]),"+f"(d[1]),"+f"(d[2]),"+f"(d[3])
        :"r"(a[0]),"r"(a[1]),"r"(a[2]),"r"(a[3]),"r"(b[0]),"r"(b[1])); }
__device__ __forceinline__ void wgrp(int n){
    if(n>=2) asm volatile("cp.async.wait_group 2;"::);
    else if(n==1) asm volatile("cp.async.wait_group 1;"::);
    else asm volatile("cp.async.wait_group 0;"::); }

// split w_h -> pre-swizzled bf16 hi/lo B tiles (block=8 units -> 32 rows)
__global__ void __launch_bounds__(256) prep_w(const float* __restrict__ w){
    const int idx=blockIdx.x*256+threadIdx.x;       // 4096 rows x 128 k8
    const int n=idx>>7, k8=idx&127;
    const int g=n>>10, j=n&1023, bx=j>>3, r=(j&7)*4+g;
    const int ch=k8>>3, kk=k8&7;
    const uint32_t off=swz((uint32_t)(r*128+kk*16));
    const float* s=w+(size_t)n*NHID+ch*64+kk*8;
    uint4 uh,ul; __nv_bfloat16*ph=(__nv_bfloat16*)&uh,*pl=(__nv_bfloat16*)&ul;
#pragma unroll
    for(int i=0;i<8;i++){ float v=s[i]; ph[i]=__float2bfloat16(v);
        pl[i]=__float2bfloat16(v-__bfloat162float(ph[i])); }
    *(uint4*)((char*)&g_wt[0][bx][ch][0]+off)=uh;
    *(uint4*)((char*)&g_wt[1][bx][ch][0]+off)=ul;
}
// split h0 -> A tiles buf 0
__global__ void __launch_bounds__(256) prep_h0(const float* __restrict__ h){
    const int idx=blockIdx.x*256+threadIdx.x;       // 64 x 128
    const int b=idx>>7, k8=idx&127, ch=k8>>3, kk=k8&7;
    const uint32_t off=swz((uint32_t)(b*128+kk*16));
    const float* s=h+(size_t)b*NHID+ch*64+kk*8;
    uint4 uh,ul; __nv_bfloat16*ph=(__nv_bfloat16*)&uh,*pl=(__nv_bfloat16*)&ul;
#pragma unroll
    for(int i=0;i<8;i++){ float v=s[i]; ph[i]=__float2bfloat16(v);
        pl[i]=__float2bfloat16(v-__bfloat162float(ph[i])); }
    *(uint4*)((char*)&g_ht[0][0][ch][0]+off)=uh;
    *(uint4*)((char*)&g_ht[1][0][ch][0]+off)=ul;
}

// persistent HMMA recurrence: 128 blocks x 256 thr (8 warps), 1 blk/SM
// smem: [0,131072) w (sp0 16x4KB | sp1); [131072,+64K) h 4 bufs x (hi8K|lo8K);
//       [196608,+9216) D 64x36 f32; [205824/206848] hh/hl staging
__global__ void __launch_bounds__(RTHR,1) lstm_mma(const float* __restrict__ c0){
    extern __shared__ char sm[];
    const uint32_t S=s2u(sm), SW=S, SH=S+131072;
    float* Ds=(float*)(sm+196608);
    uint32_t* hh=(uint32_t*)(sm+205824);
    uint32_t* hl=(uint32_t*)(sm+206848);

    const int tid=threadIdx.x, lane=tid&31, wid=tid>>5, bx=blockIdx.x, j0=bx*8;
    const int mi=wid&3, ng=wid>>2;
    const int arow=mi*16+(lane&15);
    const uint32_t aoff=arow*128, axor=(arow&7)<<4, aklo=(lane>>4)*16;
    const int brow=ng*16+(lane&7)+((lane>>4)&1)*8;
    const uint32_t boff=brow*128, bxor=(brow&7)<<4, bklo=((lane>>3)&1)*16;
    const int eb=tid&63, up=tid>>6, u0=up*2;

    // pin w slice (128 KB)
#pragma unroll
    for(int sp=0;sp<2;sp++){
        const char* src=(const char*)&g_wt[sp][bx][0][0];
#pragma unroll
        for(int q=0;q<16;q++)
            cp16(SW+sp*65536+(tid+q*256)*16, src+(size_t)(tid+q*256)*16);
    }
    asm volatile("cp.async.commit_group;"::);
    asm volatile("cp.async.wait_group 0;"::);

    float creg[2];
    creg[0]=c0[(size_t)eb*NHID+j0+u0];
    creg[1]=c0[(size_t)eb*NHID+j0+u0+1];
    __syncthreads();

    for(int t=0;t<SEQ;t++){
        const int rb=t&1, wb=rb^1;
        float xg[2][4];
        {   const float* xp=g_xw+(size_t)t*BATCH*G4+(size_t)eb*G4;
#pragma unroll
            for(int g=0;g<4;g++){
                xg[0][g]=xp[g*1024+j0+u0];
                xg[1][g]=xp[g*1024+j0+u0+1];
            }
        }
        float d0[4]={0,0,0,0}, d1[4]={0,0,0,0};

        auto loadh=[&](int cl){
            const uint32_t db=SH+(cl&3)*16384;
            const char* s0=(const char*)&g_ht[0][rb][cl][0];
            const char* s1=(const char*)&g_ht[1][rb][cl][0];
            cp16(db+tid*16,        s0+(size_t)tid*16);
            cp16(db+4096+tid*16,   s0+4096+(size_t)tid*16);
            cp16(db+8192+tid*16,   s1+(size_t)tid*16);
            cp16(db+12288+tid*16,  s1+4096+(size_t)tid*16);
            asm volatile("cp.async.commit_group;"::);
        };
        loadh(0); loadh(1); loadh(2);

        for(int c=0;c<16;c++){
            wgrp(c<=13?2:15-c);
            __syncthreads();
            if(c+3<16) loadh(c+3);
            const uint32_t hb=SH+(c&3)*16384;
            const uint32_t wc=SW+c*4096;
#pragma unroll
            for(int s=0;s<4;s++){
                uint32_t Ah[4],Al[4],Bh[4],Bl[4];
                const uint32_t ak=(uint32_t)((s*32+aklo))^axor;
                const uint32_t bk=(uint32_t)((s*32+bklo))^bxor;
                ldm4(Ah, hb+aoff+ak);
                ldm4(Al, hb+8192+aoff+ak);
                ldm4(Bh, wc+boff+bk);
                ldm4(Bl, wc+65536+boff+bk);
                hmma(d0,Ah,Bh);   hmma(d1,Ah,Bh+2);
                hmma(d0,Ah,Bl);   hmma(d1,Ah,Bl+2);
                hmma(d0,Al,Bh);   hmma(d1,Al,Bh+2);
            }
        }

        // store D frags to padded smem
        {   const int dr=mi*16+(lane>>2);
            const int dc=ng*16+(lane&3)*2;
            Ds[dr*36+dc]=d0[0];     Ds[dr*36+dc+1]=d0[1];
            Ds[(dr+8)*36+dc]=d0[2]; Ds[(dr+8)*36+dc+1]=d0[3];
            Ds[dr*36+dc+8]=d1[0];     Ds[dr*36+dc+9]=d1[1];
            Ds[(dr+8)*36+dc+8]=d1[2]; Ds[(dr+8)*36+dc+9]=d1[3];
        }
        __syncthreads();

        // epilogue: thread -> (b=eb, units u0,u0+1)
        {   float* ho=g_hs+(size_t)t*BATCH*NHID+(size_t)eb*NHID+j0+u0;
            __nv_bfloat162 phv, plv;
#pragma unroll
            for(int uu=0;uu<2;uu++){
                const float* dp=&Ds[eb*36+(u0+uu)*4];
                const float ai=dp[0]+xg[uu][0], af=dp[1]+xg[uu][1];
                const float ao=dp[2]+xg[uu][2], ag=dp[3]+xg[uu][3];
                const float iS=1.f/(1.f+expf(-ai)), fS=1.f/(1.f+expf(-af));
                const float oS=1.f/(1.f+expf(-ao)), gT=tanhf(ag);
                const float cn=fS*creg[uu]+iS*gT; creg[uu]=cn;
                const float hv=oS*tanhf(cn);
                ho[uu]=hv;
                __nv_bfloat16 hi=__float2bfloat16(hv);
                __nv_bfloat16 lo=__float2bfloat16(hv-__bfloat162float(hi));
                if(uu==0){ phv.x=hi; plv.x=lo; } else { phv.y=hi; plv.y=lo; }
            }
            hh[eb*4+up]=*(uint32_t*)&phv;
            hl[eb*4+up]=*(uint32_t*)&plv;
        }
        __syncthreads();
        if(tid<64){
            const uint32_t off=swz((uint32_t)(tid*128+(bx&7)*16));
            *(uint4*)((char*)&g_ht[0][wb][bx>>3][0]+off)=*(uint4*)&hh[tid*4];
            *(uint4*)((char*)&g_ht[1][wb][bx>>3][0]+off)=*(uint4*)&hl[tid*4];
        }
        __threadfence();
        __syncthreads();
        if(tid==0){
            volatile unsigned* gp=&g_gen;
            const unsigned old=*gp;
            __threadfence();
            if(atomicAdd(&g_arr,1u)==RBLK-1){ atomicExch(&g_arr,0u); __threadfence(); atomicAdd(&g_gen,1u); }
            else { while(*gp==old){} }
            __threadfence();
        }
        __syncthreads();
    }
    g_c[(size_t)eb*NHID+j0+u0]=creg[0];
    g_c[(size_t)eb*NHID+j0+u0+1]=creg[1];
}

// fp32 GEMM C[M,N]=A[M,K]@B[N,K]^T (+bias). 128x128, double-buffered, f32x2.
__global__ void __launch_bounds__(256) gemm_nt_bias(
    const float* __restrict__ A,const float* __restrict__ B,
    const float* __restrict__ bias,float* __restrict__ C,int M,int N,int K){
    __shared__ float As[2][8][128], Bs[2][8][128];
    const int tid=threadIdx.x, row0=blockIdx.y*128, col0=blockIdx.x*128;
    const int lr=tid>>1, lc=(tid&1)<<2, tx=tid&15, ty=tid>>4;
    unsigned long long acc[8][4];
#pragma unroll
    for(int i=0;i<8;i++){acc[i][0]=acc[i][1]=acc[i][2]=acc[i][3]=0ull;}
    const float* Ab=A+(size_t)row0*K; const float* Bb=B+(size_t)col0*K;
    const int nT=K/8;
    float4 a4=*(const float4*)(Ab+(size_t)lr*K+lc);
    float4 b4=*(const float4*)(Bb+(size_t)lr*K+lc);
    As[0][lc][lr]=a4.x;As[0][lc+1][lr]=a4.y;As[0][lc+2][lr]=a4.z;As[0][lc+3][lr]=a4.w;
    Bs[0][lc][lr]=b4.x;Bs[0][lc+1][lr]=b4.y;Bs[0][lc+2][lr]=b4.z;Bs[0][lc+3][lr]=b4.w;
    __syncthreads();
    for(int kt=0;kt<nT;kt++){
        const int cur=kt&1;
        if(kt+1<nT){
            a4=*(const float4*)(Ab+(size_t)lr*K+(kt+1)*8+lc);
            b4=*(const float4*)(Bb+(size_t)lr*K+(kt+1)*8+lc);
        }
#pragma unroll
        for(int k=0;k<8;k++){
            float ra[8];
            *(float4*)&ra[0]=*(const float4*)&As[cur][k][ty*8];
            *(float4*)&ra[4]=*(const float4*)&As[cur][k][ty*8+4];
            ulonglong2 r0=*(const ulonglong2*)&Bs[cur][k][tx*8];
            ulonglong2 r1=*(const ulonglong2*)&Bs[cur][k][tx*8+4];
#pragma unroll
            for(int i=0;i<8;i++){
                const unsigned long long pa=pk2(ra[i]);
                ffma2(acc[i][0],pa,r0.x); ffma2(acc[i][1],pa,r0.y);
                ffma2(acc[i][2],pa,r1.x); ffma2(acc[i][3],pa,r1.y);
            }
        }
        if(kt+1<nT){
            const int nx=cur^1;
            As[nx][lc][lr]=a4.x;As[nx][lc+1][lr]=a4.y;As[nx][lc+2][lr]=a4.z;As[nx][lc+3][lr]=a4.w;
            Bs[nx][lc][lr]=b4.x;Bs[nx][lc+1][lr]=b4.y;Bs[nx][lc+2][lr]=b4.z;Bs[nx][lc+3][lr]=b4.w;
            __syncthreads();
        }
    }
#pragma unroll
    for(int i=0;i<8;i++){
        const int r=row0+ty*8+i;
        float av[8];
#pragma unroll
        for(int j=0;j<4;j++) upk2(acc[i][j],av[2*j],av[2*j+1]);
#pragma unroll
        for(int j=0;j<8;j+=4){
            const int cc=col0+tx*8+j;
            float4 v={av[j],av[j+1],av[j+2],av[j+3]};
            if(bias){v.x+=bias[cc];v.y+=bias[cc+1];v.z+=bias[cc+2];v.w+=bias[cc+3];}
            *(float4*)(C+(size_t)r*N+cc)=v;
        }
    }
}

__global__ void copy_tail(float* __restrict__ oh,float* __restrict__ oc){
    const int i=blockIdx.x*blockDim.x+threadIdx.x;
    if(i<BATCH*NHID){
        oh[i]=g_hs[(size_t)(SEQ-1)*BATCH*NHID+i];
        oc[i]=g_c[i];
    }
}

extern "C" void kernel_launch(void* const* d_in,const int* in_sizes,int n_in,
                              void* d_out,int out_size){
    const float* x   =(const float*)d_in[0];
    const float* h0  =(const float*)d_in[1];
    const float* c0  =(const float*)d_in[2];
    const float* w_x =(const float*)d_in[3];
    const float* w_h =(const float*)d_in[4];
    const float* bias=(const float*)d_in[5];
    const float* w_o =(const float*)d_in[6];
    float* out=(float*)d_out;
    float *xw,*hs;
    cudaGetSymbolAddress((void**)&xw,g_xw);
    cudaGetSymbolAddress((void**)&hs,g_hs);
    static int once=0;
    if(!once){
        cudaFuncSetAttribute(lstm_mma,cudaFuncAttributeMaxDynamicSharedMemorySize,207872);
        once=1;
    }
    {   dim3 g(G4/128,(SEQ*BATCH)/128);
        gemm_nt_bias<<<g,256>>>(x,w_x,bias,xw,SEQ*BATCH,G4,NHID); }
    prep_w <<<2048,256>>>(w_h);
    prep_h0<<<32,  256>>>(h0);
    lstm_mma<<<RBLK,RTHR,207872>>>(c0);
    {   dim3 g(NHID/128,(SEQ*BATCH)/128);
        gemm_nt_bias<<<g,256>>>(hs,w_o,nullptr,out,SEQ*BATCH,NHID,NHID); }
    copy_tail<<<(BATCH*NHID+255)/256,256>>>(
        out+(size_t)SEQ*BATCH*NHID,
        out+(size_t)SEQ*BATCH*NHID+BATCH*NHID);
}

// round 8
// speedup vs baseline: 1.4041x; 1.0632x over previous
#include <cuda_runtime.h>
#include <cuda_bf16.h>
#include <math.h>
#include <stdint.h>

#define SEQ 512
#define BATCH 64
#define NHID 1024
#define G4 4096
#define RBLK 128
#define RTHR 256

__device__ float g_xw[(size_t)SEQ*BATCH*G4];
__device__ float g_hs[(size_t)SEQ*BATCH*NHID];
__device__ float g_c[(size_t)BATCH*NHID];
__device__ unsigned g_arr, g_gen;
__device__ uint4 g_wt[2][RBLK][16][256];   // [split][blk][k64-chunk][32r x 128B]
__device__ uint4 g_ht[2][2][16][512];      // [split][buf][k64-chunk][64b x 128B]

__device__ __forceinline__ unsigned long long pk2(float x){
    unsigned long long r; asm("mov.b64 %0,{%1,%1};":"=l"(r):"f"(x)); return r; }
__device__ __forceinline__ void upk2(unsigned long long v,float&a,float&b){
    asm("mov.b64 {%0,%1},%2;":"=f"(a),"=f"(b):"l"(v)); }
__device__ __forceinline__ void ffma2(unsigned long long&d,unsigned long long a,unsigned long long b){
    asm("fma.rn.f32x2 %0,%1,%2,%0;":"+l"(d):"l"(a),"l"(b)); }
__device__ __forceinline__ void cp16(uint32_t d,const void*s){
    asm volatile("cp.async.cg.shared.global [%0],[%1],16;"::"r"(d),"l"(s)); }
__device__ __forceinline__ uint32_t s2u(const void*p){
    uint32_t a; asm("{.reg .u64 t; cvta.to.shared.u64 t,%1; cvt.u32.u64 %0,t;}":"=r"(a):"l"(p)); return a; }
__host__ __device__ __forceinline__ uint32_t swz(uint32_t o){ return o^((o>>3)&0x70); }
__device__ __forceinline__ void ldm4(uint32_t*r,uint32_t a){
    asm volatile("ldmatrix.sync.aligned.m8n8.x4.shared.b16 {%0,%1,%2,%3},[%4];"
        :"=r"(r[0]),"=r"(r[1]),"=r"(r[2]),"=r"(r[3]):"r"(a)); }
__device__ __forceinline__ void hmma(float*d,const uint32_t*a,const uint32_t*b){
    asm volatile("mma.sync.aligned.m16n8k16.row.col.f32.bf16.bf16.f32 "
        "{%0,%1,%2,%3},{%4,%5,%6,%7},{%8,%9},{%0,%1,%2,%3};"
        :"+f"(d[0]),"+f"(d[1]),"+f"(d[2]),"+f"(d[3])
        :"r"(a[0]),"r"(a[1]),"r"(a[2]),"r"(a[3]),"r"(b[0]),"r"(b[1])); }
__device__ __forceinline__ void wgrp(int n){
    if(n>=2) asm volatile("cp.async.wait_group 2;"::);
    else if(n==1) asm volatile("cp.async.wait_group 1;"::);
    else asm volatile("cp.async.wait_group 0;"::); }
__device__ __forceinline__ float sigf(float x){
    return __fdividef(1.f, 1.f+__expf(-x)); }
__device__ __forceinline__ float tanhfast(float x){
    return __fdividef(2.f, 1.f+__expf(-2.f*x)) - 1.f; }

// split w_h -> pre-swizzled bf16 hi/lo B tiles (block=8 units -> 32 rows)
__global__ void __launch_bounds__(256) prep_w(const float* __restrict__ w){
    const int idx=blockIdx.x*256+threadIdx.x;       // 4096 rows x 128 k8
    const int n=idx>>7, k8=idx&127;
    const int g=n>>10, j=n&1023, bx=j>>3, r=(j&7)*4+g;
    const int ch=k8>>3, kk=k8&7;
    const uint32_t off=swz((uint32_t)(r*128+kk*16));
    const float* s=w+(size_t)n*NHID+ch*64+kk*8;
    uint4 uh,ul; __nv_bfloat16*ph=(__nv_bfloat16*)&uh,*pl=(__nv_bfloat16*)&ul;
#pragma unroll
    for(int i=0;i<8;i++){ float v=s[i]; ph[i]=__float2bfloat16(v);
        pl[i]=__float2bfloat16(v-__bfloat162float(ph[i])); }
    *(uint4*)((char*)&g_wt[0][bx][ch][0]+off)=uh;
    *(uint4*)((char*)&g_wt[1][bx][ch][0]+off)=ul;
}
// split h0 -> A tiles buf 0
__global__ void __launch_bounds__(256) prep_h0(const float* __restrict__ h){
    const int idx=blockIdx.x*256+threadIdx.x;       // 64 x 128
    const int b=idx>>7, k8=idx&127, ch=k8>>3, kk=k8&7;
    const uint32_t off=swz((uint32_t)(b*128+kk*16));
    const float* s=h+(size_t)b*NHID+ch*64+kk*8;
    uint4 uh,ul; __nv_bfloat16*ph=(__nv_bfloat16*)&uh,*pl=(__nv_bfloat16*)&ul;
#pragma unroll
    for(int i=0;i<8;i++){ float v=s[i]; ph[i]=__float2bfloat16(v);
        pl[i]=__float2bfloat16(v-__bfloat162float(ph[i])); }
    *(uint4*)((char*)&g_ht[0][0][ch][0]+off)=uh;
    *(uint4*)((char*)&g_ht[1][0][ch][0]+off)=ul;
}

// persistent HMMA recurrence v2: 128 blocks x 256 thr (8 warps), 1 blk/SM
// warps: mi=wid&1 (m-half of 64 rows), nsub=(wid>>1)&1 (n16 of 32 cols),
//        kq=wid>>2 (k16 pair within each k64 chunk). Software-pipelined frags.
// smem: [0,131072) w [split][chunk 4KB]; [131072,+64K) h 4 bufs x (hi8K|lo8K);
//       Ds[2][64][33] f32 (16.9KB) ALIASES h bufs (used post-loop only);
//       [196608] hh 1KB; [197632] hl 1KB. total 198656.
__global__ void __launch_bounds__(RTHR,1) lstm_mma(const float* __restrict__ c0){
    extern __shared__ char sm[];
    const uint32_t S=s2u(sm), SW=S, SH=S+131072;
    float* Ds=(float*)(sm+131072);
    uint32_t* hh=(uint32_t*)(sm+196608);
    uint32_t* hl=(uint32_t*)(sm+197632);

    const int tid=threadIdx.x, lane=tid&31, wid=tid>>5, bx=blockIdx.x, j0=bx*8;
    const int mi=wid&1, nsub=(wid>>1)&1, kq=wid>>2;
    // A lane addressing (rows mi*32 + ms*16 + (lane&15))
    const int ar=lane&15;
    const uint32_t aklo=(lane>>4)*16, axor=(uint32_t)((ar&7)<<4);
    uint32_t aoff[2];
#pragma unroll
    for(int ms=0;ms<2;ms++) aoff[ms]=(uint32_t)((mi*32+ms*16+ar)*128);
    // B lane addressing (rows nsub*16 + br)
    const int br=(lane&7)+((lane>>4)&1)*8;
    const uint32_t bklo=(uint32_t)(((lane>>3)&1)*16), bxor=(uint32_t)((br&7)<<4);
    const uint32_t boff=(uint32_t)((nsub*16+br)*128);
    // epilogue identity
    const int eb=tid&63, up=tid>>6, u0=up*2;

    // pin w slice (128 KB)
#pragma unroll
    for(int sp=0;sp<2;sp++){
        const char* src=(const char*)&g_wt[sp][bx][0][0];
#pragma unroll
        for(int q=0;q<16;q++)
            cp16(SW+sp*65536+(tid+q*256)*16, src+(size_t)(tid+q*256)*16);
    }
    asm volatile("cp.async.commit_group;"::);
    asm volatile("cp.async.wait_group 0;"::);

    float creg[2];
    creg[0]=c0[(size_t)eb*NHID+j0+u0];
    creg[1]=c0[(size_t)eb*NHID+j0+u0+1];
    __syncthreads();

    for(int t=0;t<SEQ;t++){
        const int rb=t&1, wb=rb^1;
        float xg[2][4];
        {   const float* xp=g_xw+(size_t)t*BATCH*G4+(size_t)eb*G4;
#pragma unroll
            for(int g=0;g<4;g++){
                xg[0][g]=xp[g*1024+j0+u0];
                xg[1][g]=xp[g*1024+j0+u0+1];
            }
        }
        float d[2][2][4];
#pragma unroll
        for(int a1=0;a1<2;a1++)
#pragma unroll
            for(int a2=0;a2<2;a2++){d[a1][a2][0]=d[a1][a2][1]=d[a1][a2][2]=d[a1][a2][3]=0.f;}

        auto loadh=[&](int cl){
            const uint32_t db=SH+(cl&3)*16384;
            const char* s0=(const char*)&g_ht[0][rb][cl][0];
            const char* s1=(const char*)&g_ht[1][rb][cl][0];
            cp16(db+tid*16,        s0+(size_t)tid*16);
            cp16(db+4096+tid*16,   s0+4096+(size_t)tid*16);
            cp16(db+8192+tid*16,   s1+(size_t)tid*16);
            cp16(db+12288+tid*16,  s1+4096+(size_t)tid*16);
            asm volatile("cp.async.commit_group;"::);
        };
        uint32_t fA0[16],fB0[8],fA1[16],fB1[8];
        auto ldfrag=[&](uint32_t* fA,uint32_t* fB,int c,int s){
            const uint32_t hb=SH+(c&3)*16384;
            const uint32_t wc=SW+c*4096;
            const uint32_t ak=(uint32_t)((kq*2+s)*32+aklo)^axor;
            const uint32_t bk=(uint32_t)((kq*2+s)*32+bklo)^bxor;
            ldm4(fA+0,  hb+aoff[0]+ak);
            ldm4(fA+4,  hb+aoff[1]+ak);
            ldm4(fA+8,  hb+8192+aoff[0]+ak);
            ldm4(fA+12, hb+8192+aoff[1]+ak);
            ldm4(fB+0,  wc+boff+bk);
            ldm4(fB+4,  wc+65536+boff+bk);
        };
        auto domma=[&](uint32_t* fA,uint32_t* fB){
#pragma unroll
            for(int ms=0;ms<2;ms++)
#pragma unroll
                for(int n8=0;n8<2;n8++){
                    hmma(d[ms][n8], fA+ms*4,   fB+n8*2);     // hi*hi
                    hmma(d[ms][n8], fA+ms*4,   fB+4+n8*2);   // hi*lo
                    hmma(d[ms][n8], fA+8+ms*4, fB+n8*2);     // lo*hi
                }
        };

        loadh(0); loadh(1); loadh(2);
        wgrp(2);           // chunk 0 arrived
        __syncthreads();
        ldfrag(fA0,fB0,0,0);

        for(int c=0;c<16;c++){
            wgrp(c<=13?1:0);       // chunks <= c+1 arrived
            __syncthreads();       // visibility + buffer-reuse guard
            if(c+3<16) loadh(c+3); // rewrites buf (c-1)&3 (reads done pre-sync)
            ldfrag(fA1,fB1,c,1);   // second k16 of this chunk
            domma(fA0,fB0);
            if(c<15) ldfrag(fA0,fB0,c+1,0);   // prefetch next chunk
            domma(fA1,fB1);
        }
        __syncthreads();   // all tile reads done; Ds may alias now

        // store D partials: Ds[kq][row][col], pitch 33
#pragma unroll
        for(int ms=0;ms<2;ms++)
#pragma unroll
            for(int n8=0;n8<2;n8++){
                const int row=mi*32+ms*16+(lane>>2);
                const int col=nsub*16+n8*8+(lane&3)*2;
                float* p=&Ds[(kq*64+row)*33+col];
                p[0]=d[ms][n8][0]; p[1]=d[ms][n8][1];
                p[33*8]=d[ms][n8][2]; p[33*8+1]=d[ms][n8][3];
            }
        __syncthreads();

        // epilogue: thread -> (b=eb, units u0,u0+1)
        {   float* ho=g_hs+(size_t)t*BATCH*NHID+(size_t)eb*NHID+j0+u0;
            __nv_bfloat162 phv, plv;
#pragma unroll
            for(int uu=0;uu<2;uu++){
                const float* p0=&Ds[(0*64+eb)*33+(u0+uu)*4];
                const float* p1=&Ds[(1*64+eb)*33+(u0+uu)*4];
                const float ai=p0[0]+p1[0]+xg[uu][0];
                const float af=p0[1]+p1[1]+xg[uu][1];
                const float ao=p0[2]+p1[2]+xg[uu][2];
                const float ag=p0[3]+p1[3]+xg[uu][3];
                const float iS=sigf(ai), fS=sigf(af), oS=sigf(ao);
                const float gT=tanhfast(ag);
                const float cn=fS*creg[uu]+iS*gT; creg[uu]=cn;
                const float hv=oS*tanhfast(cn);
                ho[uu]=hv;
                __nv_bfloat16 hi=__float2bfloat16(hv);
                __nv_bfloat16 lo=__float2bfloat16(hv-__bfloat162float(hi));
                if(uu==0){ phv.x=hi; plv.x=lo; } else { phv.y=hi; plv.y=lo; }
            }
            hh[eb*4+up]=*(uint32_t*)&phv;
            hl[eb*4+up]=*(uint32_t*)&plv;
        }
        __syncthreads();
        if(tid<64){
            const uint32_t off=swz((uint32_t)(tid*128+(bx&7)*16));
            *(uint4*)((char*)&g_ht[0][wb][bx>>3][0]+off)=*(uint4*)&hh[tid*4];
            *(uint4*)((char*)&g_ht[1][wb][bx>>3][0]+off)=*(uint4*)&hl[tid*4];
        }
        __threadfence();
        __syncthreads();
        if(tid==0){
            volatile unsigned* gp=&g_gen;
            const unsigned old=*gp;
            __threadfence();
            if(atomicAdd(&g_arr,1u)==RBLK-1){ atomicExch(&g_arr,0u); __threadfence(); atomicAdd(&g_gen,1u); }
            else { while(*gp==old){} }
            __threadfence();
        }
        __syncthreads();
    }
    g_c[(size_t)eb*NHID+j0+u0]=creg[0];
    g_c[(size_t)eb*NHID+j0+u0+1]=creg[1];
}

// fp32 GEMM C[M,N]=A[M,K]@B[N,K]^T (+bias). 128x128, double-buffered, f32x2.
__global__ void __launch_bounds__(256) gemm_nt_bias(
    const float* __restrict__ A,const float* __restrict__ B,
    const float* __restrict__ bias,float* __restrict__ C,int M,int N,int K){
    __shared__ float As[2][8][128], Bs[2][8][128];
    const int tid=threadIdx.x, row0=blockIdx.y*128, col0=blockIdx.x*128;
    const int lr=tid>>1, lc=(tid&1)<<2, tx=tid&15, ty=tid>>4;
    unsigned long long acc[8][4];
#pragma unroll
    for(int i=0;i<8;i++){acc[i][0]=acc[i][1]=acc[i][2]=acc[i][3]=0ull;}
    const float* Ab=A+(size_t)row0*K; const float* Bb=B+(size_t)col0*K;
    const int nT=K/8;
    float4 a4=*(const float4*)(Ab+(size_t)lr*K+lc);
    float4 b4=*(const float4*)(Bb+(size_t)lr*K+lc);
    As[0][lc][lr]=a4.x;As[0][lc+1][lr]=a4.y;As[0][lc+2][lr]=a4.z;As[0][lc+3][lr]=a4.w;
    Bs[0][lc][lr]=b4.x;Bs[0][lc+1][lr]=b4.y;Bs[0][lc+2][lr]=b4.z;Bs[0][lc+3][lr]=b4.w;
    __syncthreads();
    for(int kt=0;kt<nT;kt++){
        const int cur=kt&1;
        if(kt+1<nT){
            a4=*(const float4*)(Ab+(size_t)lr*K+(kt+1)*8+lc);
            b4=*(const float4*)(Bb+(size_t)lr*K+(kt+1)*8+lc);
        }
#pragma unroll
        for(int k=0;k<8;k++){
            float ra[8];
            *(float4*)&ra[0]=*(const float4*)&As[cur][k][ty*8];
            *(float4*)&ra[4]=*(const float4*)&As[cur][k][ty*8+4];
            ulonglong2 r0=*(const ulonglong2*)&Bs[cur][k][tx*8];
            ulonglong2 r1=*(const ulonglong2*)&Bs[cur][k][tx*8+4];
#pragma unroll
            for(int i=0;i<8;i++){
                const unsigned long long pa=pk2(ra[i]);
                ffma2(acc[i][0],pa,r0.x); ffma2(acc[i][1],pa,r0.y);
                ffma2(acc[i][2],pa,r1.x); ffma2(acc[i][3],pa,r1.y);
            }
        }
        if(kt+1<nT){
            const int nx=cur^1;
            As[nx][lc][lr]=a4.x;As[nx][lc+1][lr]=a4.y;As[nx][lc+2][lr]=a4.z;As[nx][lc+3][lr]=a4.w;
            Bs[nx][lc][lr]=b4.x;Bs[nx][lc+1][lr]=b4.y;Bs[nx][lc+2][lr]=b4.z;Bs[nx][lc+3][lr]=b4.w;
            __syncthreads();
        }
    }
#pragma unroll
    for(int i=0;i<8;i++){
        const int r=row0+ty*8+i;
        float av[8];
#pragma unroll
        for(int j=0;j<4;j++) upk2(acc[i][j],av[2*j],av[2*j+1]);
#pragma unroll
        for(int j=0;j<8;j+=4){
            const int cc=col0+tx*8+j;
            float4 v={av[j],av[j+1],av[j+2],av[j+3]};
            if(bias){v.x+=bias[cc];v.y+=bias[cc+1];v.z+=bias[cc+2];v.w+=bias[cc+3];}
            *(float4*)(C+(size_t)r*N+cc)=v;
        }
    }
}

__global__ void copy_tail(float* __restrict__ oh,float* __restrict__ oc){
    const int i=blockIdx.x*blockDim.x+threadIdx.x;
    if(i<BATCH*NHID){
        oh[i]=g_hs[(size_t)(SEQ-1)*BATCH*NHID+i];
        oc[i]=g_c[i];
    }
}

extern "C" void kernel_launch(void* const* d_in,const int* in_sizes,int n_in,
                              void* d_out,int out_size){
    const float* x   =(const float*)d_in[0];
    const float* h0  =(const float*)d_in[1];
    const float* c0  =(const float*)d_in[2];
    const float* w_x =(const float*)d_in[3];
    const float* w_h =(const float*)d_in[4];
    const float* bias=(const float*)d_in[5];
    const float* w_o =(const float*)d_in[6];
    float* out=(float*)d_out;
    float *xw,*hs;
    cudaGetSymbolAddress((void**)&xw,g_xw);
    cudaGetSymbolAddress((void**)&hs,g_hs);
    static int once=0;
    if(!once){
        cudaFuncSetAttribute(lstm_mma,cudaFuncAttributeMaxDynamicSharedMemorySize,198656);
        once=1;
    }
    {   dim3 g(G4/128,(SEQ*BATCH)/128);
        gemm_nt_bias<<<g,256>>>(x,w_x,bias,xw,SEQ*BATCH,G4,NHID); }
    prep_w <<<2048,256>>>(w_h);
    prep_h0<<<32,  256>>>(h0);
    lstm_mma<<<RBLK,RTHR,198656>>>(c0);
    {   dim3 g(NHID/128,(SEQ*BATCH)/128);
        gemm_nt_bias<<<g,256>>>(hs,w_o,nullptr,out,SEQ*BATCH,NHID,NHID); }
    copy_tail<<<(BATCH*NHID+255)/256,256>>>(
        out+(size_t)SEQ*BATCH*NHID,
        out+(size_t)SEQ*BATCH*NHID+BATCH*NHID);
}

// round 9
// speedup vs baseline: 1.4764x; 1.0515x over previous
#include <cuda_runtime.h>
#include <cuda_bf16.h>
#include <math.h>
#include <stdint.h>

#define SEQ 512
#define BATCH 64
#define NHID 1024
#define G4 4096
#define RBLK 128
#define RTHR 512

__device__ float g_xw[(size_t)SEQ*BATCH*G4];
__device__ float g_hs[(size_t)SEQ*BATCH*NHID];
__device__ float g_c[(size_t)BATCH*NHID];
__device__ unsigned g_gen;
__device__ unsigned g_flags[RBLK];
__device__ uint4 g_wt[2][RBLK][16][256];   // [split][blk][k64-chunk][32r x 128B]
__device__ uint4 g_ht[2][2][16][512];      // [split][buf][k64-chunk][64b x 128B]

__device__ __forceinline__ unsigned long long pk2(float x){
    unsigned long long r; asm("mov.b64 %0,{%1,%1};":"=l"(r):"f"(x)); return r; }
__device__ __forceinline__ void upk2(unsigned long long v,float&a,float&b){
    asm("mov.b64 {%0,%1},%2;":"=f"(a),"=f"(b):"l"(v)); }
__device__ __forceinline__ void ffma2(unsigned long long&d,unsigned long long a,unsigned long long b){
    asm("fma.rn.f32x2 %0,%1,%2,%0;":"+l"(d):"l"(a),"l"(b)); }
__device__ __forceinline__ void cp16(uint32_t d,const void*s){
    asm volatile("cp.async.cg.shared.global [%0],[%1],16;"::"r"(d),"l"(s)); }
__device__ __forceinline__ uint32_t s2u(const void*p){
    uint32_t a; asm("{.reg .u64 t; cvta.to.shared.u64 t,%1; cvt.u32.u64 %0,t;}":"=r"(a):"l"(p)); return a; }
__host__ __device__ __forceinline__ uint32_t swz(uint32_t o){ return o^((o>>3)&0x70); }
__device__ __forceinline__ void ldm4(uint32_t*r,uint32_t a){
    asm volatile("ldmatrix.sync.aligned.m8n8.x4.shared.b16 {%0,%1,%2,%3},[%4];"
        :"=r"(r[0]),"=r"(r[1]),"=r"(r[2]),"=r"(r[3]):"r"(a)); }
__device__ __forceinline__ void hmma(float*d,const uint32_t*a,const uint32_t*b){
    asm volatile("mma.sync.aligned.m16n8k16.row.col.f32.bf16.bf16.f32 "
        "{%0,%1,%2,%3},{%4,%5,%6,%7},{%8,%9},{%0,%1,%2,%3};"
        :"+f"(d[0]),"+f"(d[1]),"+f"(d[2]),"+f"(d[3])
        :"r"(a[0]),"r"(a[1]),"r"(a[2]),"r"(a[3]),"r"(b[0]),"r"(b[1])); }
__device__ __forceinline__ void wgrp(int n){
    if(n>=2) asm volatile("cp.async.wait_group 2;"::);
    else if(n==1) asm volatile("cp.async.wait_group 1;"::);
    else asm volatile("cp.async.wait_group 0;"::); }
__device__ __forceinline__ float sigf(float x){
    return __fdividef(1.f, 1.f+__expf(-x)); }
__device__ __forceinline__ float tanhfast(float x){
    return __fdividef(2.f, 1.f+__expf(-2.f*x)) - 1.f; }

// split w_h -> pre-swizzled bf16 hi/lo B tiles (block=8 units -> 32 rows)
__global__ void __launch_bounds__(256) prep_w(const float* __restrict__ w){
    const int idx=blockIdx.x*256+threadIdx.x;       // 4096 rows x 128 k8
    const int n=idx>>7, k8=idx&127;
    const int g=n>>10, j=n&1023, bx=j>>3, r=(j&7)*4+g;
    const int ch=k8>>3, kk=k8&7;
    const uint32_t off=swz((uint32_t)(r*128+kk*16));
    const float* s=w+(size_t)n*NHID+ch*64+kk*8;
    uint4 uh,ul; __nv_bfloat16*ph=(__nv_bfloat16*)&uh,*pl=(__nv_bfloat16*)&ul;
#pragma unroll
    for(int i=0;i<8;i++){ float v=s[i]; ph[i]=__float2bfloat16(v);
        pl[i]=__float2bfloat16(v-__bfloat162float(ph[i])); }
    *(uint4*)((char*)&g_wt[0][bx][ch][0]+off)=uh;
    *(uint4*)((char*)&g_wt[1][bx][ch][0]+off)=ul;
}
// split h0 -> A tiles buf 0
__global__ void __launch_bounds__(256) prep_h0(const float* __restrict__ h){
    const int idx=blockIdx.x*256+threadIdx.x;       // 64 x 128
    const int b=idx>>7, k8=idx&127, ch=k8>>3, kk=k8&7;
    const uint32_t off=swz((uint32_t)(b*128+kk*16));
    const float* s=h+(size_t)b*NHID+ch*64+kk*8;
    uint4 uh,ul; __nv_bfloat16*ph=(__nv_bfloat16*)&uh,*pl=(__nv_bfloat16*)&ul;
#pragma unroll
    for(int i=0;i<8;i++){ float v=s[i]; ph[i]=__float2bfloat16(v);
        pl[i]=__float2bfloat16(v-__bfloat162float(ph[i])); }
    *(uint4*)((char*)&g_ht[0][0][ch][0]+off)=uh;
    *(uint4*)((char*)&g_ht[1][0][ch][0]+off)=ul;
}

// persistent HMMA recurrence v3: 128 blocks x 512 thr (16 warps), 1 blk/SM
// warps: mi=wid&1 (m-half), nsub=(wid>>1)&1 (n16), kq=wid>>2 (k16 in chunk).
// smem: [0,131072) w [split][chunk 4KB]; [131072,+64K) h 4 bufs x (hi8K|lo8K);
//       Ds[4][64][33] f32 (33.8KB) ALIASES h bufs; [196608] hh 1KB; [197632] hl.
__global__ void __launch_bounds__(RTHR,1) lstm_mma(const float* __restrict__ c0){
    extern __shared__ char sm[];
    const uint32_t S=s2u(sm), SW=S, SH=S+131072;
    float* Ds=(float*)(sm+131072);
    __nv_bfloat16* hhp=(__nv_bfloat16*)(sm+196608);
    __nv_bfloat16* hlp=(__nv_bfloat16*)(sm+197632);

    const int tid=threadIdx.x, lane=tid&31, wid=tid>>5, bx=blockIdx.x, j0=bx*8;
    const int mi=wid&1, nsub=(wid>>1)&1, kq=wid>>2;
    const int ar=lane&15;
    const uint32_t aklo=(uint32_t)((lane>>4)*16), axor=(uint32_t)((ar&7)<<4);
    uint32_t aoff[2];
#pragma unroll
    for(int ms=0;ms<2;ms++) aoff[ms]=(uint32_t)((mi*32+ms*16+ar)*128);
    const int br=(lane&7)+((lane>>4)&1)*8;
    const uint32_t bklo=(uint32_t)(((lane>>3)&1)*16), bxor=(uint32_t)((br&7)<<4);
    const uint32_t boff=(uint32_t)((nsub*16+br)*128);
    const int eb=tid>>3, eu=tid&7;   // epilogue: batch, unit

    // pin w slice (128 KB)
#pragma unroll
    for(int sp=0;sp<2;sp++){
        const char* src=(const char*)&g_wt[sp][bx][0][0];
#pragma unroll
        for(int q=0;q<8;q++)
            cp16(SW+sp*65536+(tid+q*512)*16, src+(size_t)(tid+q*512)*16);
    }
    asm volatile("cp.async.commit_group;"::);
    asm volatile("cp.async.wait_group 0;"::);

    float creg=c0[(size_t)eb*NHID+j0+eu];
    const unsigned g0=*(volatile unsigned*)&g_gen;
    __syncthreads();

    for(int t=0;t<SEQ;t++){
        const int rb=t&1, wb=rb^1;
        float xg[4];
        {   const float* xp=g_xw+(size_t)t*BATCH*G4+(size_t)eb*G4+j0+eu;
#pragma unroll
            for(int g=0;g<4;g++) xg[g]=xp[g*1024];
        }
        float d[2][2][4];
#pragma unroll
        for(int a1=0;a1<2;a1++)
#pragma unroll
            for(int a2=0;a2<2;a2++){d[a1][a2][0]=d[a1][a2][1]=d[a1][a2][2]=d[a1][a2][3]=0.f;}

        auto loadh=[&](int cl){
            const uint32_t db=SH+(cl&3)*16384;
            cp16(db+tid*16,      (const char*)&g_ht[0][rb][cl][0]+(size_t)tid*16);
            cp16(db+8192+tid*16, (const char*)&g_ht[1][rb][cl][0]+(size_t)tid*16);
            asm volatile("cp.async.commit_group;"::);
        };
        uint32_t fA0[16],fB0[8],fA1[16],fB1[8];
        auto ldfrag=[&](uint32_t* fA,uint32_t* fB,int c){
            const uint32_t hb=SH+(c&3)*16384;
            const uint32_t wc=SW+c*4096;
            const uint32_t ak=((uint32_t)(kq*32)+aklo)^axor;
            const uint32_t bk=((uint32_t)(kq*32)+bklo)^bxor;
            ldm4(fA+0,  hb+aoff[0]+ak);
            ldm4(fA+4,  hb+aoff[1]+ak);
            ldm4(fA+8,  hb+4096+aoff[0]+ak);
            ldm4(fA+12, hb+4096+aoff[1]+ak);
            ldm4(fB+0,  wc+boff+bk);
            ldm4(fB+4,  wc+65536+boff+bk);
        };
        auto domma=[&](uint32_t* fA,uint32_t* fB){
#pragma unroll
            for(int ms=0;ms<2;ms++)
#pragma unroll
                for(int n8=0;n8<2;n8++){
                    hmma(d[ms][n8], fA+ms*4,   fB+n8*2);     // hi*hi
                    hmma(d[ms][n8], fA+ms*4,   fB+4+n8*2);   // hi*lo(w)
                    hmma(d[ms][n8], fA+8+ms*4, fB+n8*2);     // lo(h)*hi
                }
        };
        // NOTE: h bufs are (hi 8K | lo 8K) per chunk of 64k: hi rows 64x128B=8K;
        // lo at +8192. A hi row stride 128B covers k 0..63 (chunk-local).
        // aoff indexes into an 8KB half: rows*128, half selected by +0/+8192.
        // (ldfrag uses +4096? -> rows are 64, 64*128=8192; lo at +8192.) fix:
        // handled below via corrected ldfrag2.
        auto ldfrag2=[&](uint32_t* fA,uint32_t* fB,int c){
            const uint32_t hb=SH+(c&3)*16384;
            const uint32_t wc=SW+c*4096;
            const uint32_t ak=((uint32_t)(kq*32)+aklo)^axor;
            const uint32_t bk=((uint32_t)(kq*32)+bklo)^bxor;
            ldm4(fA+0,  hb+aoff[0]+ak);
            ldm4(fA+4,  hb+aoff[1]+ak);
            ldm4(fA+8,  hb+8192+aoff[0]+ak);
            ldm4(fA+12, hb+8192+aoff[1]+ak);
            ldm4(fB+0,  wc+boff+bk);
            ldm4(fB+4,  wc+65536+boff+bk);
        };

        loadh(0); loadh(1); loadh(2);
        wgrp(2);                 // chunk 0 arrived
        __syncthreads();
        ldfrag2(fA0,fB0,0);

        for(int c=0;c<16;c++){
            if(c+3<16) loadh(c+3);          // overwrites buf (c-1)&3 (reads ended iter c-2)
            wgrp(c<=12?2:(c==13?1:0));      // chunks <= c+1 arrived
            __syncthreads();
            if(c<15) ldfrag2(fA1,fB1,c+1);
            domma(fA0,fB0);
#pragma unroll
            for(int z=0;z<16;z++) fA0[z]=fA1[z];
#pragma unroll
            for(int z=0;z<8;z++)  fB0[z]=fB1[z];
        }
        __syncthreads();   // all h-buf reads done; Ds may alias now

        // store D partials: Ds[kq][row][col], pitch 33
#pragma unroll
        for(int ms=0;ms<2;ms++)
#pragma unroll
            for(int n8=0;n8<2;n8++){
                const int row=mi*32+ms*16+(lane>>2);
                const int col=nsub*16+n8*8+(lane&3)*2;
                float* p=&Ds[(kq*64+row)*33+col];
                p[0]=d[ms][n8][0]; p[1]=d[ms][n8][1];
                p[33*8]=d[ms][n8][2]; p[33*8+1]=d[ms][n8][3];
            }
        __syncthreads();

        // epilogue: thread -> (b=eb, unit eu)
        {   float a0=xg[0],a1=xg[1],a2=xg[2],a3=xg[3];
#pragma unroll
            for(int q=0;q<4;q++){
                const float* p=&Ds[(q*64+eb)*33+eu*4];
                a0+=p[0]; a1+=p[1]; a2+=p[2]; a3+=p[3];
            }
            const float iS=sigf(a0), fS=sigf(a1), oS=sigf(a2);
            const float gT=tanhfast(a3);
            const float cn=fS*creg+iS*gT; creg=cn;
            const float hv=oS*tanhfast(cn);
            g_hs[(size_t)t*BATCH*NHID+(size_t)eb*NHID+j0+eu]=hv;
            const __nv_bfloat16 hi=__float2bfloat16(hv);
            hhp[eb*8+eu]=hi;
            hlp[eb*8+eu]=__float2bfloat16(hv-__bfloat162float(hi));
        }
        __syncthreads();
        if(tid<64){
            const uint32_t off=swz((uint32_t)(tid*128+(bx&7)*16));
            *(uint4*)((char*)&g_ht[0][wb][bx>>3][0]+off)=*(uint4*)&hhp[tid*8];
            *(uint4*)((char*)&g_ht[1][wb][bx>>3][0]+off)=*(uint4*)&hlp[tid*8];
        }
        // ---- flag-based grid barrier ----
        __threadfence();
        __syncthreads();
        if(tid==0) ((volatile unsigned*)g_flags)[bx]=g0+(unsigned)t+1u;
        if(bx==0){
            if(tid<RBLK){ volatile unsigned* f=g_flags+tid;
                while(*f < g0+(unsigned)t+1u){} }
            __syncthreads();
            if(tid==0){ __threadfence(); *(volatile unsigned*)&g_gen=g0+(unsigned)t+1u; }
        }else{
            if(tid==0){ volatile unsigned* gp=&g_gen;
                while(*gp < g0+(unsigned)t+1u){} }
            __syncthreads();
        }
    }
    g_c[(size_t)eb*NHID+j0+eu]=creg;
}

// fp32 GEMM C[M,N]=A[M,K]@B[N,K]^T (+bias). 128x128, double-buffered, f32x2.
__global__ void __launch_bounds__(256) gemm_nt_bias(
    const float* __restrict__ A,const float* __restrict__ B,
    const float* __restrict__ bias,float* __restrict__ C,int M,int N,int K){
    __shared__ float As[2][8][128], Bs[2][8][128];
    const int tid=threadIdx.x, row0=blockIdx.y*128, col0=blockIdx.x*128;
    const int lr=tid>>1, lc=(tid&1)<<2, tx=tid&15, ty=tid>>4;
    unsigned long long acc[8][4];
#pragma unroll
    for(int i=0;i<8;i++){acc[i][0]=acc[i][1]=acc[i][2]=acc[i][3]=0ull;}
    const float* Ab=A+(size_t)row0*K; const float* Bb=B+(size_t)col0*K;
    const int nT=K/8;
    float4 a4=*(const float4*)(Ab+(size_t)lr*K+lc);
    float4 b4=*(const float4*)(Bb+(size_t)lr*K+lc);
    As[0][lc][lr]=a4.x;As[0][lc+1][lr]=a4.y;As[0][lc+2][lr]=a4.z;As[0][lc+3][lr]=a4.w;
    Bs[0][lc][lr]=b4.x;Bs[0][lc+1][lr]=b4.y;Bs[0][lc+2][lr]=b4.z;Bs[0][lc+3][lr]=b4.w;
    __syncthreads();
    for(int kt=0;kt<nT;kt++){
        const int cur=kt&1;
        if(kt+1<nT){
            a4=*(const float4*)(Ab+(size_t)lr*K+(kt+1)*8+lc);
            b4=*(const float4*)(Bb+(size_t)lr*K+(kt+1)*8+lc);
        }
#pragma unroll
        for(int k=0;k<8;k++){
            float ra[8];
            *(float4*)&ra[0]=*(const float4*)&As[cur][k][ty*8];
            *(float4*)&ra[4]=*(const float4*)&As[cur][k][ty*8+4];
            ulonglong2 r0=*(const ulonglong2*)&Bs[cur][k][tx*8];
            ulonglong2 r1=*(const ulonglong2*)&Bs[cur][k][tx*8+4];
#pragma unroll
            for(int i=0;i<8;i++){
                const unsigned long long pa=pk2(ra[i]);
                ffma2(acc[i][0],pa,r0.x); ffma2(acc[i][1],pa,r0.y);
                ffma2(acc[i][2],pa,r1.x); ffma2(acc[i][3],pa,r1.y);
            }
        }
        if(kt+1<nT){
            const int nx=cur^1;
            As[nx][lc][lr]=a4.x;As[nx][lc+1][lr]=a4.y;As[nx][lc+2][lr]=a4.z;As[nx][lc+3][lr]=a4.w;
            Bs[nx][lc][lr]=b4.x;Bs[nx][lc+1][lr]=b4.y;Bs[nx][lc+2][lr]=b4.z;Bs[nx][lc+3][lr]=b4.w;
            __syncthreads();
        }
    }
#pragma unroll
    for(int i=0;i<8;i++){
        const int r=row0+ty*8+i;
        float av[8];
#pragma unroll
        for(int j=0;j<4;j++) upk2(acc[i][j],av[2*j],av[2*j+1]);
#pragma unroll
        for(int j=0;j<8;j+=4){
            const int cc=col0+tx*8+j;
            float4 v={av[j],av[j+1],av[j+2],av[j+3]};
            if(bias){v.x+=bias[cc];v.y+=bias[cc+1];v.z+=bias[cc+2];v.w+=bias[cc+3];}
            *(float4*)(C+(size_t)r*N+cc)=v;
        }
    }
}

__global__ void copy_tail(float* __restrict__ oh,float* __restrict__ oc){
    const int i=blockIdx.x*blockDim.x+threadIdx.x;
    if(i<BATCH*NHID){
        oh[i]=g_hs[(size_t)(SEQ-1)*BATCH*NHID+i];
        oc[i]=g_c[i];
    }
}

extern "C" void kernel_launch(void* const* d_in,const int* in_sizes,int n_in,
                              void* d_out,int out_size){
    const float* x   =(const float*)d_in[0];
    const float* h0  =(const float*)d_in[1];
    const float* c0  =(const float*)d_in[2];
    const float* w_x =(const float*)d_in[3];
    const float* w_h =(const float*)d_in[4];
    const float* bias=(const float*)d_in[5];
    const float* w_o =(const float*)d_in[6];
    float* out=(float*)d_out;
    float *xw,*hs;
    cudaGetSymbolAddress((void**)&xw,g_xw);
    cudaGetSymbolAddress((void**)&hs,g_hs);
    static int once=0;
    if(!once){
        cudaFuncSetAttribute(lstm_mma,cudaFuncAttributeMaxDynamicSharedMemorySize,198656);
        once=1;
    }
    {   dim3 g(G4/128,(SEQ*BATCH)/128);
        gemm_nt_bias<<<g,256>>>(x,w_x,bias,xw,SEQ*BATCH,G4,NHID); }
    prep_w <<<2048,256>>>(w_h);
    prep_h0<<<32,  256>>>(h0);
    lstm_mma<<<RBLK,RTHR,198656>>>(c0);
    {   dim3 g(NHID/128,(SEQ*BATCH)/128);
        gemm_nt_bias<<<g,256>>>(hs,w_o,nullptr,out,SEQ*BATCH,NHID,NHID); }
    copy_tail<<<(BATCH*NHID+255)/256,256>>>(
        out+(size_t)SEQ*BATCH*NHID,
        out+(size_t)SEQ*BATCH*NHID+BATCH*NHID);
}

// round 10
// speedup vs baseline: 2.5794x; 1.7472x over previous
#include <cuda_runtime.h>
#include <cuda_bf16.h>
#include <math.h>
#include <stdint.h>

#define SEQ 512
#define BATCH 64
#define NHID 1024
#define G4 4096
#define RBLK 128
#define RTHR 512

__device__ float g_xw[(size_t)SEQ*BATCH*G4];
__device__ float g_c[(size_t)BATCH*NHID];
__device__ unsigned g_gen;
__device__ unsigned g_flags[RBLK];
__device__ uint4 g_wt[2][RBLK][16][256];        // recurrence w tiles
__device__ uint4 g_hsplit[2][SEQ+1][16][512];   // h tiles per step [split][t]
__device__ uint4 g_xt[2][512][16][512];         // x tiles (32768 rows)
__device__ uint4 g_wxt[2][64][16][512];         // w_x tiles (4096 rows)
__device__ uint4 g_wot[2][16][16][512];         // w_o tiles (1024 rows)

__device__ __forceinline__ void cp16(uint32_t d,const void*s){
    asm volatile("cp.async.cg.shared.global [%0],[%1],16;"::"r"(d),"l"(s)); }
__device__ __forceinline__ uint32_t s2u(const void*p){
    uint32_t a; asm("{.reg .u64 t; cvta.to.shared.u64 t,%1; cvt.u32.u64 %0,t;}":"=r"(a):"l"(p)); return a; }
__host__ __device__ __forceinline__ uint32_t swz(uint32_t o){ return o^((o>>3)&0x70); }
__device__ __forceinline__ void ldm4(uint32_t*r,uint32_t a){
    asm volatile("ldmatrix.sync.aligned.m8n8.x4.shared.b16 {%0,%1,%2,%3},[%4];"
        :"=r"(r[0]),"=r"(r[1]),"=r"(r[2]),"=r"(r[3]):"r"(a)); }
__device__ __forceinline__ void hmma(float*d,const uint32_t*a,const uint32_t*b){
    asm volatile("mma.sync.aligned.m16n8k16.row.col.f32.bf16.bf16.f32 "
        "{%0,%1,%2,%3},{%4,%5,%6,%7},{%8,%9},{%0,%1,%2,%3};"
        :"+f"(d[0]),"+f"(d[1]),"+f"(d[2]),"+f"(d[3])
        :"r"(a[0]),"r"(a[1]),"r"(a[2]),"r"(a[3]),"r"(b[0]),"r"(b[1])); }
__device__ __forceinline__ void wgrp(int n){
    if(n>=2) asm volatile("cp.async.wait_group 2;"::);
    else if(n==1) asm volatile("cp.async.wait_group 1;"::);
    else asm volatile("cp.async.wait_group 0;"::); }
__device__ __forceinline__ float sigf(float x){
    return __fdividef(1.f, 1.f+__expf(-x)); }
__device__ __forceinline__ float tanhfast(float x){
    return __fdividef(2.f, 1.f+__expf(-2.f*x)) - 1.f; }

// generic fp32 [R][1024] -> pre-swizzled bf16 hi/lo tiles [R/64][16][64][128B]
__global__ void __launch_bounds__(256) prep_tiles(const float* __restrict__ src,
        uint4* __restrict__ th, uint4* __restrict__ tl){
    const int idx=blockIdx.x*256+threadIdx.x;
    const int r=idx>>7, k8=idx&127, ch=k8>>3, kk=k8&7, rb=r>>6, rr=r&63;
    const size_t off=((size_t)(rb*16+ch))*8192 + swz((uint32_t)(rr*128+kk*16));
    const float* s=src+(size_t)r*1024+ch*64+kk*8;
    uint4 uh,ul; __nv_bfloat16*ph=(__nv_bfloat16*)&uh,*pl=(__nv_bfloat16*)&ul;
#pragma unroll
    for(int i=0;i<8;i++){ float v=s[i]; ph[i]=__float2bfloat16(v);
        pl[i]=__float2bfloat16(v-__bfloat162float(ph[i])); }
    *(uint4*)((char*)th+off)=uh;
    *(uint4*)((char*)tl+off)=ul;
}

// recurrence w tiles (block=8 units -> 32 gate rows)
__global__ void __launch_bounds__(256) prep_w(const float* __restrict__ w){
    const int idx=blockIdx.x*256+threadIdx.x;
    const int n=idx>>7, k8=idx&127;
    const int g=n>>10, j=n&1023, bx=j>>3, r=(j&7)*4+g;
    const int ch=k8>>3, kk=k8&7;
    const uint32_t off=swz((uint32_t)(r*128+kk*16));
    const float* s=w+(size_t)n*NHID+ch*64+kk*8;
    uint4 uh,ul; __nv_bfloat16*ph=(__nv_bfloat16*)&uh,*pl=(__nv_bfloat16*)&ul;
#pragma unroll
    for(int i=0;i<8;i++){ float v=s[i]; ph[i]=__float2bfloat16(v);
        pl[i]=__float2bfloat16(v-__bfloat162float(ph[i])); }
    *(uint4*)((char*)&g_wt[0][bx][ch][0]+off)=uh;
    *(uint4*)((char*)&g_wt[1][bx][ch][0]+off)=ul;
}

// HMMA GEMM: C[M,N] = A[M,1024] @ B[N,1024]^T (+bias), bf16-split-3.
// A,B given as pre-swizzled hi/lo tile arrays. Block 128x128, 8 warps m32xn64.
#define GBS 65536
__global__ void __launch_bounds__(256,1) hmma_gemm(
    const char* __restrict__ Ah, const char* __restrict__ Al,
    const char* __restrict__ Bh, const char* __restrict__ Bl,
    float* __restrict__ C, const float* __restrict__ bias, int N)
{
    extern __shared__ char sm[];
    const uint32_t S=s2u(sm);
    const int tid=threadIdx.x, lane=tid&31, wid=tid>>5;
    const int rb0=blockIdx.y*2, cb0=blockIdx.x*2;
    const int mi=wid&3, ni=wid>>2;
    const int ar=lane&15;
    const uint32_t axor=(uint32_t)((ar&7)<<4), ahalf=(uint32_t)((lane>>4)*16);
    uint32_t aro[2];
#pragma unroll
    for(int ms=0;ms<2;ms++) aro[ms]=(uint32_t)((mi*32+ms*16+ar)*128);
    const int br=(lane&7)+((lane>>4)&1)*8;
    const uint32_t bxor=(uint32_t)((br&7)<<4), bhalf=(uint32_t)(((lane>>3)&1)*16);

    float d[2][8][4];
#pragma unroll
    for(int a1=0;a1<2;a1++)
#pragma unroll
        for(int a2=0;a2<8;a2++){d[a1][a2][0]=d[a1][a2][1]=d[a1][a2][2]=d[a1][a2][3]=0.f;}

    auto load=[&](int ch){
        const uint32_t bb=S+(uint32_t)(ch%3)*GBS;
#pragma unroll
        for(int q=0;q<8;q++){
            const uint32_t o=(uint32_t)(tid+q*256)*16;
            const int sp=o>>14; const uint32_t rem=o&16383;
            const int rh=rem>>13; const uint32_t win=rem&8191;
            cp16(bb+o, (sp?Al:Ah)+((size_t)((rb0+rh)*16+ch))*8192+win);
        }
#pragma unroll
        for(int q=0;q<8;q++){
            const uint32_t o=(uint32_t)(tid+q*256)*16;
            const int sp=o>>14; const uint32_t rem=o&16383;
            const int rh=rem>>13; const uint32_t win=rem&8191;
            cp16(bb+32768+o, (sp?Bl:Bh)+((size_t)((cb0+rh)*16+ch))*8192+win);
        }
        asm volatile("cp.async.commit_group;"::);
    };

    load(0); load(1);
    for(int c=0;c<16;c++){
        wgrp(c<=14?1:0);
        __syncthreads();
        if(c+2<16) load(c+2);
        const uint32_t AB=S+(uint32_t)(c%3)*GBS;
#pragma unroll
        for(int kq=0;kq<4;kq++){
            const uint32_t ak=((uint32_t)(kq*32)+ahalf)^axor;
            const uint32_t bk=((uint32_t)(kq*32)+bhalf)^bxor;
            uint32_t fA[16];
#pragma unroll
            for(int ms=0;ms<2;ms++)
#pragma unroll
                for(int sp=0;sp<2;sp++)
                    ldm4(fA+ms*8+sp*4, AB+sp*16384+aro[ms]+ak);
#pragma unroll
            for(int n16=0;n16<4;n16++){
                uint32_t fBh[4],fBl[4];
                const uint32_t bro=(uint32_t)((ni*64+n16*16+br)*128);
                ldm4(fBh, AB+32768+bro+bk);
                ldm4(fBl, AB+32768+16384+bro+bk);
#pragma unroll
                for(int ms=0;ms<2;ms++)
#pragma unroll
                    for(int h8=0;h8<2;h8++){
                        float* dd=d[ms][n16*2+h8];
                        hmma(dd, fA+ms*8,   fBh+h8*2);   // hi*hi
                        hmma(dd, fA+ms*8,   fBl+h8*2);   // hi*lo
                        hmma(dd, fA+ms*8+4, fBh+h8*2);   // lo*hi
                    }
            }
        }
    }
    const int row0=blockIdx.y*128, col0=blockIdx.x*128;
#pragma unroll
    for(int ms=0;ms<2;ms++)
#pragma unroll
        for(int n8=0;n8<8;n8++){
            const int r=row0+mi*32+ms*16+(lane>>2);
            const int cc=col0+ni*64+n8*8+(lane&3)*2;
            float b0=0.f,b1=0.f;
            if(bias){ b0=bias[cc]; b1=bias[cc+1]; }
            float2 v0={d[ms][n8][0]+b0, d[ms][n8][1]+b1};
            float2 v1={d[ms][n8][2]+b0, d[ms][n8][3]+b1};
            *(float2*)(C+(size_t)r*N+cc)=v0;
            *(float2*)(C+(size_t)(r+8)*N+cc)=v1;
        }
}

// persistent HMMA recurrence (v3, tiles indexed by step)
__global__ void __launch_bounds__(RTHR,1) lstm_mma(const float* __restrict__ c0){
    extern __shared__ char sm[];
    const uint32_t S=s2u(sm), SW=S, SH=S+131072;
    float* Ds=(float*)(sm+131072);
    __nv_bfloat16* hhp=(__nv_bfloat16*)(sm+196608);
    __nv_bfloat16* hlp=(__nv_bfloat16*)(sm+197632);

    const int tid=threadIdx.x, lane=tid&31, wid=tid>>5, bx=blockIdx.x, j0=bx*8;
    const int mi=wid&1, nsub=(wid>>1)&1, kq=wid>>2;
    const int ar=lane&15;
    const uint32_t aklo=(uint32_t)((lane>>4)*16), axor=(uint32_t)((ar&7)<<4);
    uint32_t aoff[2];
#pragma unroll
    for(int ms=0;ms<2;ms++) aoff[ms]=(uint32_t)((mi*32+ms*16+ar)*128);
    const int br=(lane&7)+((lane>>4)&1)*8;
    const uint32_t bklo=(uint32_t)(((lane>>3)&1)*16), bxor=(uint32_t)((br&7)<<4);
    const uint32_t boff=(uint32_t)((nsub*16+br)*128);
    const int eb=tid>>3, eu=tid&7;

#pragma unroll
    for(int sp=0;sp<2;sp++){
        const char* src=(const char*)&g_wt[sp][bx][0][0];
#pragma unroll
        for(int q=0;q<8;q++)
            cp16(SW+sp*65536+(tid+q*512)*16, src+(size_t)(tid+q*512)*16);
    }
    asm volatile("cp.async.commit_group;"::);
    asm volatile("cp.async.wait_group 0;"::);

    float creg=c0[(size_t)eb*NHID+j0+eu];
    const unsigned g0=*(volatile unsigned*)&g_gen;
    __syncthreads();

    for(int t=0;t<SEQ;t++){
        float xg[4];
        {   const float* xp=g_xw+(size_t)t*BATCH*G4+(size_t)eb*G4+j0+eu;
#pragma unroll
            for(int g=0;g<4;g++) xg[g]=xp[g*1024];
        }
        float d[2][2][4];
#pragma unroll
        for(int a1=0;a1<2;a1++)
#pragma unroll
            for(int a2=0;a2<2;a2++){d[a1][a2][0]=d[a1][a2][1]=d[a1][a2][2]=d[a1][a2][3]=0.f;}

        auto loadh=[&](int cl){
            const uint32_t db=SH+(cl&3)*16384;
            cp16(db+tid*16,      (const char*)&g_hsplit[0][t][cl][0]+(size_t)tid*16);
            cp16(db+8192+tid*16, (const char*)&g_hsplit[1][t][cl][0]+(size_t)tid*16);
            asm volatile("cp.async.commit_group;"::);
        };
        uint32_t fA0[16],fB0[8],fA1[16],fB1[8];
        auto ldfrag2=[&](uint32_t* fA,uint32_t* fB,int c){
            const uint32_t hb=SH+(c&3)*16384;
            const uint32_t wc=SW+c*4096;
            const uint32_t ak=((uint32_t)(kq*32)+aklo)^axor;
            const uint32_t bk=((uint32_t)(kq*32)+bklo)^bxor;
            ldm4(fA+0,  hb+aoff[0]+ak);
            ldm4(fA+4,  hb+aoff[1]+ak);
            ldm4(fA+8,  hb+8192+aoff[0]+ak);
            ldm4(fA+12, hb+8192+aoff[1]+ak);
            ldm4(fB+0,  wc+boff+bk);
            ldm4(fB+4,  wc+65536+boff+bk);
        };
        auto domma=[&](uint32_t* fA,uint32_t* fB){
#pragma unroll
            for(int ms=0;ms<2;ms++)
#pragma unroll
                for(int n8=0;n8<2;n8++){
                    hmma(d[ms][n8], fA+ms*4,   fB+n8*2);
                    hmma(d[ms][n8], fA+ms*4,   fB+4+n8*2);
                    hmma(d[ms][n8], fA+8+ms*4, fB+n8*2);
                }
        };

        loadh(0); loadh(1); loadh(2);
        wgrp(2);
        __syncthreads();
        ldfrag2(fA0,fB0,0);

        for(int c=0;c<16;c++){
            if(c+3<16) loadh(c+3);
            wgrp(c<=12?2:(c==13?1:0));
            __syncthreads();
            if(c<15) ldfrag2(fA1,fB1,c+1);
            domma(fA0,fB0);
#pragma unroll
            for(int z=0;z<16;z++) fA0[z]=fA1[z];
#pragma unroll
            for(int z=0;z<8;z++)  fB0[z]=fB1[z];
        }
        __syncthreads();

#pragma unroll
        for(int ms=0;ms<2;ms++)
#pragma unroll
            for(int n8=0;n8<2;n8++){
                const int row=mi*32+ms*16+(lane>>2);
                const int col=nsub*16+n8*8+(lane&3)*2;
                float* p=&Ds[(kq*64+row)*33+col];
                p[0]=d[ms][n8][0]; p[1]=d[ms][n8][1];
                p[33*8]=d[ms][n8][2]; p[33*8+1]=d[ms][n8][3];
            }
        __syncthreads();

        {   float a0=xg[0],a1=xg[1],a2=xg[2],a3=xg[3];
#pragma unroll
            for(int q=0;q<4;q++){
                const float* p=&Ds[(q*64+eb)*33+eu*4];
                a0+=p[0]; a1+=p[1]; a2+=p[2]; a3+=p[3];
            }
            const float iS=sigf(a0), fS=sigf(a1), oS=sigf(a2);
            const float gT=tanhfast(a3);
            const float cn=fS*creg+iS*gT; creg=cn;
            const float hv=oS*tanhfast(cn);
            const __nv_bfloat16 hi=__float2bfloat16(hv);
            hhp[eb*8+eu]=hi;
            hlp[eb*8+eu]=__float2bfloat16(hv-__bfloat162float(hi));
        }
        __syncthreads();
        if(tid<64){
            const uint32_t off=swz((uint32_t)(tid*128+(bx&7)*16));
            *(uint4*)((char*)&g_hsplit[0][t+1][bx>>3][0]+off)=*(uint4*)&hhp[tid*8];
            *(uint4*)((char*)&g_hsplit[1][t+1][bx>>3][0]+off)=*(uint4*)&hlp[tid*8];
        }
        __threadfence();
        __syncthreads();
        if(tid==0) ((volatile unsigned*)g_flags)[bx]=g0+(unsigned)t+1u;
        if(bx==0){
            if(tid<RBLK){ volatile unsigned* f=g_flags+tid;
                while(*f < g0+(unsigned)t+1u){} }
            __syncthreads();
            if(tid==0){ __threadfence(); *(volatile unsigned*)&g_gen=g0+(unsigned)t+1u; }
        }else{
            if(tid==0){ volatile unsigned* gp=&g_gen;
                while(*gp < g0+(unsigned)t+1u){} }
            __syncthreads();
        }
    }
    g_c[(size_t)eb*NHID+j0+eu]=creg;
}

__global__ void copy_tail(float* __restrict__ oh,float* __restrict__ oc){
    const int i=blockIdx.x*blockDim.x+threadIdx.x;
    if(i<BATCH*NHID){
        const int b=i>>10, k=i&1023, ch=k>>6;
        const uint32_t off=swz((uint32_t)(b*128+(k&63)*2));
        const float hi=__bfloat162float(*(const __nv_bfloat16*)((const char*)&g_hsplit[0][SEQ][ch][0]+off));
        const float lo=__bfloat162float(*(const __nv_bfloat16*)((const char*)&g_hsplit[1][SEQ][ch][0]+off));
        oh[i]=hi+lo;
        oc[i]=g_c[i];
    }
}

extern "C" void kernel_launch(void* const* d_in,const int* in_sizes,int n_in,
                              void* d_out,int out_size){
    const float* x   =(const float*)d_in[0];
    const float* h0  =(const float*)d_in[1];
    const float* c0  =(const float*)d_in[2];
    const float* w_x =(const float*)d_in[3];
    const float* w_h =(const float*)d_in[4];
    const float* bias=(const float*)d_in[5];
    const float* w_o =(const float*)d_in[6];
    float* out=(float*)d_out;
    float *xw;
    cudaGetSymbolAddress((void**)&xw,g_xw);
    uint4 *xt,*wxt,*wot,*hsp;
    cudaGetSymbolAddress((void**)&xt, g_xt);
    cudaGetSymbolAddress((void**)&wxt,g_wxt);
    cudaGetSymbolAddress((void**)&wot,g_wot);
    cudaGetSymbolAddress((void**)&hsp,g_hsplit);
    const size_t XSP=(size_t)512*16*512;        // uint4 per x split
    const size_t WXSP=(size_t)64*16*512;
    const size_t WOSP=(size_t)16*16*512;
    const size_t HSP1=(size_t)16*512;           // uint4 per h step
    const size_t HSPS=(size_t)(SEQ+1)*16*512;   // uint4 per h split

    static int once=0;
    if(!once){
        cudaFuncSetAttribute(lstm_mma, cudaFuncAttributeMaxDynamicSharedMemorySize,198656);
        cudaFuncSetAttribute(hmma_gemm,cudaFuncAttributeMaxDynamicSharedMemorySize,196608);
        once=1;
    }

    // tile preps
    prep_tiles<<<16384,256>>>(x,   xt,        xt+XSP);
    prep_tiles<<<2048, 256>>>(w_x, wxt,       wxt+WXSP);
    prep_tiles<<<512,  256>>>(w_o, wot,       wot+WOSP);
    prep_tiles<<<32,   256>>>(h0,  hsp,       hsp+HSPS);
    prep_w    <<<2048, 256>>>(w_h);

    // Phase 1: xw = x@w_x^T + bias  (M=32768, N=4096)
    {   dim3 g(G4/128,(SEQ*BATCH)/128);
        hmma_gemm<<<g,256,196608>>>((char*)xt,(char*)(xt+XSP),
                                    (char*)wxt,(char*)(wxt+WXSP),
                                    xw,bias,G4); }
    // Phase 2: recurrence
    lstm_mma<<<RBLK,RTHR,198656>>>(c0);
    // Phase 3: pred = H@w_o^T (A = h tiles, steps 1..512)
    {   dim3 g(NHID/128,(SEQ*BATCH)/128);
        hmma_gemm<<<g,256,196608>>>((char*)(hsp+HSP1),(char*)(hsp+HSPS+HSP1),
                                    (char*)wot,(char*)(wot+WOSP),
                                    out,nullptr,NHID); }
    copy_tail<<<(BATCH*NHID+255)/256,256>>>(
        out+(size_t)SEQ*BATCH*NHID,
        out+(size_t)SEQ*BATCH*NHID+BATCH*NHID);
}